// round 3
// baseline (speedup 1.0000x reference)
#include <cuda_runtime.h>
#include <cstdint>

// Problem dims
#define Bn 256
#define Tn 512
#define In 256
#define Hn 1024
#define On 128
#define Gn 2048   // 2*H

#define RGRID    128
#define RTHREADS 256

// Scratch (static device globals — no allocation)
__device__ float    g_Xp[Bn * Gn];      // 2 MB : precomputed x-projection + Bih
__device__ float    g_h[2][Hn];         // double-buffered hidden state
__device__ float    g_lasts[Bn * Hn];   // 1 MB : h after each step
__device__ unsigned g_bar[Bn];          // per-step grid barrier counters

// ---------------------------------------------------------------------------
// Phase 0: Xp[b, j] = dot(inputs[b, 511, :], Wih[j, :]) + Bih[j]
// grid (256 j-groups of 8, 8 b-groups of 32), 256 threads (8 warps).
// Warp owns one j (weights in registers), loops 32 b's, shfl-reduces.
// Block (0,0) also zeroes the barrier counters and h0 (per-launch reset so
// the captured graph replays deterministically).
// ---------------------------------------------------------------------------
__global__ void __launch_bounds__(256) xproj_kernel(
    const float* __restrict__ inputs, const float* __restrict__ Wih,
    const float* __restrict__ Bih)
{
    const int lane = threadIdx.x & 31;
    const int w    = threadIdx.x >> 5;
    const int j    = blockIdx.x * 8 + w;     // 0..2047
    const int b0   = blockIdx.y * 32;

    if (blockIdx.x == 0 && blockIdx.y == 0) {
        g_bar[threadIdx.x] = 0u;                               // 256 counters
        reinterpret_cast<float4*>(g_h[0])[threadIdx.x] =       // 1024 floats
            make_float4(0.f, 0.f, 0.f, 0.f);
    }

    const float4* wr = reinterpret_cast<const float4*>(Wih + (size_t)j * In);
    const float4 w0 = __ldg(wr + lane);        // elems lane*4 .. +3
    const float4 w1 = __ldg(wr + 32 + lane);   // elems 128 + lane*4 .. +3
    const float  bi = __ldg(Bih + j);

    #pragma unroll 2
    for (int bb = 0; bb < 32; ++bb) {
        const int b = b0 + bb;
        const float4* xr = reinterpret_cast<const float4*>(
            inputs + ((size_t)b * Tn + (Tn - 1)) * In);
        const float4 x0 = __ldg(xr + lane);
        const float4 x1 = __ldg(xr + 32 + lane);
        float a = 0.f, c = 0.f;
        a = fmaf(w0.x, x0.x, a); c = fmaf(w0.y, x0.y, c);
        a = fmaf(w0.z, x0.z, a); c = fmaf(w0.w, x0.w, c);
        a = fmaf(w1.x, x1.x, a); c = fmaf(w1.y, x1.y, c);
        a = fmaf(w1.z, x1.z, a); c = fmaf(w1.w, x1.w, c);
        float acc = a + c;
        #pragma unroll
        for (int off = 16; off > 0; off >>= 1)
            acc += __shfl_xor_sync(0xffffffffu, acc, off);
        if (lane == 0) g_Xp[(size_t)b * Gn + j] = acc + bi;
    }
}

// ---------------------------------------------------------------------------
// Phase 1: persistent recurrence. 128 CTAs (<148 SMs, 1 CTA/SM => all
// co-resident), 256 threads = 8 warps. Warp (cta, w) owns element
// j = cta*8 + w, with Whh[j,:] and Whh[j+H,:] resident in registers.
// One grid barrier per step; h is double-buffered in global (L2-resident).
// ---------------------------------------------------------------------------
__global__ void __launch_bounds__(RTHREADS, 1) recur_kernel(
    const float* __restrict__ Whh, const float* __restrict__ Bhh)
{
    __shared__ float4 hs4[Hn / 4];    // 4 KB staging of current h
    const int tid  = threadIdx.x;
    const int lane = tid & 31;
    const int w    = tid >> 5;
    const int j    = blockIdx.x * 8 + w;      // 0..1023

    // Weight rows in registers: lane holds elems {c*128 + lane*4 .. +3}
    float4 wf[8], wh[8];
    #pragma unroll
    for (int c = 0; c < 8; ++c) {
        wf[c] = __ldg(reinterpret_cast<const float4*>(
                      Whh + (size_t)j * Hn + c * 128 + lane * 4));
        wh[c] = __ldg(reinterpret_cast<const float4*>(
                      Whh + (size_t)(j + Hn) * Hn + c * 128 + lane * 4));
    }
    const float bf = __ldg(Bhh + j);
    const float bh = __ldg(Bhh + j + Hn);

    for (int b = 0; b < Bn; ++b) {
        // Prefetch this step's x-projection (read-only, L1 OK)
        const float xf = __ldg(&g_Xp[(size_t)b * Gn + j]);
        const float xh = __ldg(&g_Xp[(size_t)b * Gn + Hn + j]);

        // Stage h (produced by peers last step) — must bypass L1
        const float4* hp4 = reinterpret_cast<const float4*>(g_h[b & 1]);
        hs4[tid] = __ldcg(hp4 + tid);
        __syncthreads();

        // Dual dot products: hf = <Whh[j], h>, hh = <Whh[j+H], h>
        float a0=0.f,a1=0.f,a2=0.f,a3=0.f, c0=0.f,c1=0.f,c2=0.f,c3=0.f;
        #pragma unroll
        for (int c = 0; c < 8; ++c) {
            const float4 hv = hs4[c * 32 + lane];   // conflict-free LDS.128
            a0 = fmaf(wf[c].x, hv.x, a0);
            a1 = fmaf(wf[c].y, hv.y, a1);
            a2 = fmaf(wf[c].z, hv.z, a2);
            a3 = fmaf(wf[c].w, hv.w, a3);
            c0 = fmaf(wh[c].x, hv.x, c0);
            c1 = fmaf(wh[c].y, hv.y, c1);
            c2 = fmaf(wh[c].z, hv.z, c2);
            c3 = fmaf(wh[c].w, hv.w, c3);
        }
        float af = (a0 + a1) + (a2 + a3);
        float ah = (c0 + c1) + (c2 + c3);
        #pragma unroll
        for (int off = 16; off > 0; off >>= 1) {
            af += __shfl_xor_sync(0xffffffffu, af, off);
            ah += __shfl_xor_sync(0xffffffffu, ah, off);
        }

        // Gating (all lanes hold the sums; lane 0 commits)
        const float hprev = reinterpret_cast<const float*>(hs4)[j];
        const float fz = xf + af + bf;
        const float fG = 1.0f / (1.0f + expf(-fz));
        const float hG = tanhf(xh + fG * (ah + bh));
        const float hnew = (1.0f - fG) * hprev + fG * hG;

        if (lane == 0) {
            g_h[(b + 1) & 1][j]       = hnew;
            g_lasts[(size_t)b * Hn + j] = hnew;
        }

        // --- grid barrier (one per step; double buffering makes it enough)
        __threadfence();        // release h writes to L2
        __syncthreads();        // whole CTA done with this step
        if (tid == 0) {
            atomicAdd(&g_bar[b], 1u);
            unsigned v;
            do {
                asm volatile("ld.acquire.gpu.u32 %0, [%1];"
                             : "=r"(v) : "l"(g_bar + b) : "memory");
            } while (v < (unsigned)gridDim.x);
        }
        __syncthreads();
    }
}

// ---------------------------------------------------------------------------
// Phase 2: out[b, o] = dot(lasts[b, :], Wout[o, :]) + Bout[o]
// grid (16 o-groups of 8, 16 b-groups of 16), warp per o with register weights.
// ---------------------------------------------------------------------------
__global__ void __launch_bounds__(256) out_kernel(
    const float* __restrict__ Wout, const float* __restrict__ Bout,
    float* __restrict__ out)
{
    const int lane = threadIdx.x & 31;
    const int w    = threadIdx.x >> 5;
    const int o    = blockIdx.x * 8 + w;      // 0..127
    const int b0   = blockIdx.y * 16;

    const float4* wr = reinterpret_cast<const float4*>(Wout + (size_t)o * Hn);
    float4 wv[8];
    #pragma unroll
    for (int c = 0; c < 8; ++c) wv[c] = __ldg(wr + c * 32 + lane);
    const float bo = __ldg(Bout + o);

    for (int bb = 0; bb < 16; ++bb) {
        const int b = b0 + bb;
        const float4* lr = reinterpret_cast<const float4*>(
            g_lasts + (size_t)b * Hn);
        float a0=0.f,a1=0.f,a2=0.f,a3=0.f;
        #pragma unroll
        for (int c = 0; c < 8; ++c) {
            const float4 lv = __ldg(lr + c * 32 + lane);
            a0 = fmaf(wv[c].x, lv.x, a0);
            a1 = fmaf(wv[c].y, lv.y, a1);
            a2 = fmaf(wv[c].z, lv.z, a2);
            a3 = fmaf(wv[c].w, lv.w, a3);
        }
        float acc = (a0 + a1) + (a2 + a3);
        #pragma unroll
        for (int off = 16; off > 0; off >>= 1)
            acc += __shfl_xor_sync(0xffffffffu, acc, off);
        if (lane == 0) out[(size_t)b * On + o] = acc + bo;
    }
}

// ---------------------------------------------------------------------------
extern "C" void kernel_launch(void* const* d_in, const int* in_sizes, int n_in,
                              void* d_out, int out_size) {
    const float* inputs = (const float*)d_in[0];
    const float* Wih    = (const float*)d_in[1];
    const float* Whh    = (const float*)d_in[2];
    const float* Bih    = (const float*)d_in[3];
    const float* Bhh    = (const float*)d_in[4];
    const float* Wout   = (const float*)d_in[5];
    const float* Bout   = (const float*)d_in[6];
    float* out = (float*)d_out;

    xproj_kernel<<<dim3(256, 8), 256>>>(inputs, Wih, Bih);
    recur_kernel<<<RGRID, RTHREADS>>>(Whh, Bhh);
    out_kernel<<<dim3(16, 16), 256>>>(Wout, Bout, out);
}

// round 4
// speedup vs baseline: 1.0535x; 1.0535x over previous
#include <cuda_runtime.h>
#include <cstdint>

// Problem dims
#define Bn 256
#define Tn 512
#define In 256
#define Hn 1024
#define On 128
#define Gn 2048   // 2*H

#define RGRID 128            // recurrence CTAs (barrier arrivals)
#define OGRID 16             // output-GEMV CTAs (consumers only)
#define TGRID (RGRID + OGRID)

// Scratch (static device globals — no allocation)
__device__ float    g_Xp[Bn * Gn];      // 2 MB : x-projection + Bih
__device__ float    g_h[2][Hn];         // double-buffered hidden state
__device__ float    g_lasts[Bn * Hn];   // 1 MB : h after each step
__device__ unsigned g_bar[Bn];          // per-step grid barrier counters

__device__ __forceinline__ void bar_arrive_release(unsigned* p) {
    asm volatile("red.release.gpu.global.add.u32 [%0], 1;" :: "l"(p) : "memory");
}
__device__ __forceinline__ unsigned ld_acquire_gpu(const unsigned* p) {
    unsigned v;
    asm volatile("ld.acquire.gpu.global.u32 %0, [%1];" : "=r"(v) : "l"(p) : "memory");
    return v;
}

// ---------------------------------------------------------------------------
// Phase 0: Xp[b, j] = dot(inputs[b, T-1, :], Wih[j, :]) + Bih[j]
// grid (128 j-groups of 16, 8 b-groups of 32), 256 threads (8 warps).
// Input rows staged in smem (32 KB) so weight/input traffic is L2-served once.
// Warp owns 2 j's with weights in registers. Block (0,0) resets barrier
// counters + h0 so the captured graph replays deterministically.
// ---------------------------------------------------------------------------
__global__ void __launch_bounds__(256) xproj_kernel(
    const float* __restrict__ inputs, const float* __restrict__ Wih,
    const float* __restrict__ Bih)
{
    __shared__ float4 xs[32 * 64];   // 32 rows x 256 floats = 32 KB
    const int tid  = threadIdx.x;
    const int lane = tid & 31;
    const int w    = tid >> 5;
    const int b0   = blockIdx.y * 32;

    if (blockIdx.x == 0 && blockIdx.y == 0) {
        g_bar[tid] = 0u;                                        // 256 counters
        reinterpret_cast<float4*>(g_h[0])[tid] =                // 1024 floats
            make_float4(0.f, 0.f, 0.f, 0.f);
    }

    // Stage the 32 input rows (last timestep of each b in this group)
    #pragma unroll
    for (int i = 0; i < 8; ++i) {
        const int idx = tid + i * 256;        // 0..2047
        const int r   = idx >> 6;             // row in chunk
        const int c   = idx & 63;             // float4 col
        xs[idx] = __ldcg(reinterpret_cast<const float4*>(
            inputs + ((size_t)(b0 + r) * Tn + (Tn - 1)) * In) + c);
    }
    __syncthreads();

    // Two j's per warp, weights in registers
    const int j0 = blockIdx.x * 16 + w * 2;
    const float4* wr0 = reinterpret_cast<const float4*>(Wih + (size_t)j0 * In);
    const float4* wr1 = reinterpret_cast<const float4*>(Wih + (size_t)(j0 + 1) * In);
    const float4 wa0 = __ldg(wr0 + lane),      wa1 = __ldg(wr0 + 32 + lane);
    const float4 wb0 = __ldg(wr1 + lane),      wb1 = __ldg(wr1 + 32 + lane);
    const float  bi0 = __ldg(Bih + j0),        bi1 = __ldg(Bih + j0 + 1);

    for (int bb = 0; bb < 32; ++bb) {
        const float4 x0 = xs[bb * 64 + lane];
        const float4 x1 = xs[bb * 64 + 32 + lane];
        float a = 0.f, b = 0.f;
        a = fmaf(wa0.x, x0.x, a); a = fmaf(wa0.y, x0.y, a);
        a = fmaf(wa0.z, x0.z, a); a = fmaf(wa0.w, x0.w, a);
        a = fmaf(wa1.x, x1.x, a); a = fmaf(wa1.y, x1.y, a);
        a = fmaf(wa1.z, x1.z, a); a = fmaf(wa1.w, x1.w, a);
        b = fmaf(wb0.x, x0.x, b); b = fmaf(wb0.y, x0.y, b);
        b = fmaf(wb0.z, x0.z, b); b = fmaf(wb0.w, x0.w, b);
        b = fmaf(wb1.x, x1.x, b); b = fmaf(wb1.y, x1.y, b);
        b = fmaf(wb1.z, x1.z, b); b = fmaf(wb1.w, x1.w, b);
        #pragma unroll
        for (int off = 16; off > 0; off >>= 1) {
            a += __shfl_xor_sync(0xffffffffu, a, off);
            b += __shfl_xor_sync(0xffffffffu, b, off);
        }
        if (lane == 0) {
            g_Xp[(size_t)(b0 + bb) * Gn + j0]     = a + bi0;
            g_Xp[(size_t)(b0 + bb) * Gn + j0 + 1] = b + bi1;
        }
    }
}

// ---------------------------------------------------------------------------
// Phase 1+2 fused persistent kernel.
//   CTAs [0,128): recurrence. Warp owns j = cta*8 + w; Whh rows in registers.
//     Per step: stage h (smem, ld.cg), dual dot + shfl reduce, fast gating,
//     write h_new + lasts, then release-atomic grid barrier (no membar).
//   CTAs [128,144): output GEMV. Warp owns o; polls g_bar[b], then
//     out[b,o] = dot(lasts[b,:], Wout[o,:]) + Bout[o], one step behind.
// All 144 CTAs co-resident (<= 152 SMs, 1 CTA/SM). Out CTAs never gate the
// recurrence, so the design is fail-safe even without residency.
// ---------------------------------------------------------------------------
__global__ void __launch_bounds__(256, 1) recur_kernel(
    const float* __restrict__ Whh, const float* __restrict__ Bhh,
    const float* __restrict__ Wout, const float* __restrict__ Bout,
    float* __restrict__ out)
{
    const int tid  = threadIdx.x;
    const int lane = tid & 31;
    const int w    = tid >> 5;

    if (blockIdx.x < RGRID) {
        // ----------------- recurrence role -----------------
        __shared__ float4 hs4[Hn / 4];            // 4 KB h staging
        const int j = blockIdx.x * 8 + w;         // 0..1023

        float4 wf[8], wh[8];
        #pragma unroll
        for (int c = 0; c < 8; ++c) {
            wf[c] = __ldg(reinterpret_cast<const float4*>(
                          Whh + (size_t)j * Hn) + c * 32 + lane);
            wh[c] = __ldg(reinterpret_cast<const float4*>(
                          Whh + (size_t)(j + Hn) * Hn) + c * 32 + lane);
        }
        const float bf = __ldg(Bhh + j);
        const float bh = __ldg(Bhh + j + Hn);

        // software-pipelined x-projection loads
        float xf = __ldg(&g_Xp[j]);
        float xh = __ldg(&g_Xp[Hn + j]);

        for (int b = 0; b < Bn; ++b) {
            // stage h (peers' step-(b-1) output) — bypass L1
            const float4* hp4 = reinterpret_cast<const float4*>(g_h[b & 1]);
            hs4[tid] = __ldcg(hp4 + tid);
            __syncthreads();

            float a0=0.f,a1=0.f,a2=0.f,a3=0.f, c0=0.f,c1=0.f,c2=0.f,c3=0.f;
            #pragma unroll
            for (int c = 0; c < 8; ++c) {
                const float4 hv = hs4[c * 32 + lane];   // conflict-free LDS.128
                a0 = fmaf(wf[c].x, hv.x, a0);
                a1 = fmaf(wf[c].y, hv.y, a1);
                a2 = fmaf(wf[c].z, hv.z, a2);
                a3 = fmaf(wf[c].w, hv.w, a3);
                c0 = fmaf(wh[c].x, hv.x, c0);
                c1 = fmaf(wh[c].y, hv.y, c1);
                c2 = fmaf(wh[c].z, hv.z, c2);
                c3 = fmaf(wh[c].w, hv.w, c3);
            }
            float af = (a0 + a1) + (a2 + a3);
            float ah = (c0 + c1) + (c2 + c3);

            // prefetch next step's Xp — latency hides under reduce + barrier
            float xf_n = 0.f, xh_n = 0.f;
            if (b + 1 < Bn) {
                xf_n = __ldg(&g_Xp[(size_t)(b + 1) * Gn + j]);
                xh_n = __ldg(&g_Xp[(size_t)(b + 1) * Gn + Hn + j]);
            }

            #pragma unroll
            for (int off = 16; off > 0; off >>= 1) {
                af += __shfl_xor_sync(0xffffffffu, af, off);
                ah += __shfl_xor_sync(0xffffffffu, ah, off);
            }

            // fast gating (error ~1e-6, tolerance 1e-3)
            const float hprev = reinterpret_cast<const float*>(hs4)[j];
            const float fz = xf + af + bf;
            const float fG = __fdividef(1.0f, 1.0f + __expf(-fz));
            float ta = xh + fG * (ah + bh);
            ta = fminf(fmaxf(ta, -15.f), 15.f);
            const float e2 = __expf(2.0f * ta);
            const float hG = __fdividef(e2 - 1.0f, e2 + 1.0f);
            const float hnew = fmaf(fG, hG - hprev, hprev);  // (1-f)h + f*g

            if (lane == 0) {
                g_h[(b + 1) & 1][j]         = hnew;
                g_lasts[(size_t)b * Hn + j] = hnew;
            }

            // grid barrier: weak stores -> bar.sync -> release atomic
            // (cooperative-groups pattern; no membar, no L1 flush)
            __syncthreads();
            if (tid == 0) {
                bar_arrive_release(&g_bar[b]);
                while (ld_acquire_gpu(&g_bar[b]) < (unsigned)RGRID) {}
            }
            __syncthreads();

            xf = xf_n; xh = xh_n;
        }
    } else {
        // ----------------- output GEMV role -----------------
        const int o = (blockIdx.x - RGRID) * 8 + w;    // 0..127

        float4 wv[8];
        #pragma unroll
        for (int c = 0; c < 8; ++c)
            wv[c] = __ldg(reinterpret_cast<const float4*>(
                          Wout + (size_t)o * Hn) + c * 32 + lane);
        const float bo = __ldg(Bout + o);

        for (int b = 0; b < Bn; ++b) {
            if (tid == 0) {
                while (ld_acquire_gpu(&g_bar[b]) < (unsigned)RGRID) {}
            }
            __syncthreads();

            const float4* lr = reinterpret_cast<const float4*>(
                g_lasts + (size_t)b * Hn);
            float a0=0.f,a1=0.f,a2=0.f,a3=0.f;
            #pragma unroll
            for (int c = 0; c < 8; ++c) {
                const float4 lv = __ldcg(lr + c * 32 + lane);
                a0 = fmaf(wv[c].x, lv.x, a0);
                a1 = fmaf(wv[c].y, lv.y, a1);
                a2 = fmaf(wv[c].z, lv.z, a2);
                a3 = fmaf(wv[c].w, lv.w, a3);
            }
            float acc = (a0 + a1) + (a2 + a3);
            #pragma unroll
            for (int off = 16; off > 0; off >>= 1)
                acc += __shfl_xor_sync(0xffffffffu, acc, off);
            if (lane == 0) out[(size_t)b * On + o] = acc + bo;
        }
    }
}

// ---------------------------------------------------------------------------
extern "C" void kernel_launch(void* const* d_in, const int* in_sizes, int n_in,
                              void* d_out, int out_size) {
    const float* inputs = (const float*)d_in[0];
    const float* Wih    = (const float*)d_in[1];
    const float* Whh    = (const float*)d_in[2];
    const float* Bih    = (const float*)d_in[3];
    const float* Bhh    = (const float*)d_in[4];
    const float* Wout   = (const float*)d_in[5];
    const float* Bout   = (const float*)d_in[6];
    float* out = (float*)d_out;

    xproj_kernel<<<dim3(128, 8), 256>>>(inputs, Wih, Bih);
    recur_kernel<<<TGRID, 256>>>(Whh, Bhh, Wout, Bout, out);
}